// round 14
// baseline (speedup 1.0000x reference)
#include <cuda_runtime.h>
#include <cuda_bf16.h>
#include <math.h>
#include <stdint.h>

#define LL 1024
#define BB 128
#define DD 256
#define HH 256
#define SS (BB * HH)          // per-step stride in out

#define XN (LL * BB * DD)
#define WN (HH * DD)

// Pre-split bf16 scratch (static device arrays — allowed)
__device__ __align__(16) __nv_bfloat16 g_xhi[XN];
__device__ __align__(16) __nv_bfloat16 g_xlo[XN];
__device__ __align__(16) __nv_bfloat16 g_whi[WN];
__device__ __align__(16) __nv_bfloat16 g_wlo[WN];

__device__ __forceinline__ uint32_t smem_u32(const void* p) {
    uint32_t a;
    asm("{ .reg .u64 t; cvta.to.shared.u64 t, %1; cvt.u32.u64 %0, t; }"
        : "=r"(a) : "l"(p));
    return a;
}

// Packed f32x2 FMA
__device__ __forceinline__ unsigned long long ffma2(
    unsigned long long a, unsigned long long b, unsigned long long c)
{
    unsigned long long d;
    asm("fma.rn.f32x2 %0, %1, %2, %3;" : "=l"(d) : "l"(a), "l"(b), "l"(c));
    return d;
}
__device__ __forceinline__ float upk_sum(unsigned long long p)
{
    float lo, hi;
    asm("mov.b64 {%0, %1}, %2;" : "=f"(lo), "=f"(hi) : "l"(p));
    return lo + hi;
}

__device__ __forceinline__ void split2(float a, float b, uint32_t& h, uint32_t& l) {
    __nv_bfloat16 ha = __float2bfloat16(a);
    __nv_bfloat16 hb = __float2bfloat16(b);
    float ra = a - __bfloat162float(ha);
    float rb = b - __bfloat162float(hb);
    __nv_bfloat16 la = __float2bfloat16(ra);
    __nv_bfloat16 lb = __float2bfloat16(rb);
    h = (uint32_t)reinterpret_cast<unsigned short&>(ha) |
        ((uint32_t)reinterpret_cast<unsigned short&>(hb) << 16);
    l = (uint32_t)reinterpret_cast<unsigned short&>(la) |
        ((uint32_t)reinterpret_cast<unsigned short&>(lb) << 16);
}

// cp.async helpers
__device__ __forceinline__ void cp16(uint32_t s, const void* g) {
    asm volatile("cp.async.cg.shared.global [%0], [%1], 16;" :: "r"(s), "l"(g));
}
#define CP_COMMIT() asm volatile("cp.async.commit_group;" ::: "memory")
template <int N>
__device__ __forceinline__ void cp_wait() {
    asm volatile("cp.async.wait_group %0;" :: "n"(N) : "memory");
}

// ====================================================================
// Kernel 0: one-shot fp32 -> split-bf16 (hi, lo) for X and Wx.
// ====================================================================
#define CV_JOBS ((XN + WN) / 4)

__global__ __launch_bounds__(256) void convert_kernel(
    const float* __restrict__ X, const float* __restrict__ Wx)
{
    int i = blockIdx.x * 256 + threadIdx.x;
    if (i >= CV_JOBS) return;
    float4 v;
    if (i < XN / 4) v = ((const float4*)X)[i];
    else            v = ((const float4*)Wx)[i - XN / 4];
    uint2 hi, lo;
    split2(v.x, v.y, hi.x, lo.x);
    split2(v.z, v.w, hi.y, lo.y);
    if (i < XN / 4) {
        *(uint2*)(g_xhi + (size_t)i * 4) = hi;
        *(uint2*)(g_xlo + (size_t)i * 4) = lo;
    } else {
        size_t o = (size_t)(i - XN / 4) * 4;
        *(uint2*)(g_whi + o) = hi;
        *(uint2*)(g_wlo + o) = lo;
    }
}

// ====================================================================
// Kernel 1: xproj GEMM (R13 version, known good) — sub-chunk
// double-buffered cp.async pipeline, mma.sync bf16 split-3.
// ====================================================================
#define SC_K   32
#define NSC    8
#define ST_B   80
#define ST_TILE (128 * ST_B)
#define SB_AHI 0
#define SB_ALO ST_TILE
#define SB_WHI (2 * ST_TILE)
#define SB_WLO (3 * ST_TILE)
#define SB_BUF (4 * ST_TILE)
#define XP_SMEM (2 * SB_BUF)

__device__ __forceinline__ void ldm_x4(uint32_t& r0, uint32_t& r1,
                                       uint32_t& r2, uint32_t& r3, uint32_t addr) {
    asm volatile("ldmatrix.sync.aligned.m8n8.x4.shared.b16 {%0,%1,%2,%3}, [%4];"
                 : "=r"(r0), "=r"(r1), "=r"(r2), "=r"(r3) : "r"(addr));
}

__device__ __forceinline__ void mma16816(float* c, const uint32_t* a,
                                         uint32_t b0, uint32_t b1) {
    asm volatile(
        "mma.sync.aligned.m16n8k16.row.col.f32.bf16.bf16.f32 "
        "{%0,%1,%2,%3}, {%4,%5,%6,%7}, {%8,%9}, {%0,%1,%2,%3};"
        : "+f"(c[0]), "+f"(c[1]), "+f"(c[2]), "+f"(c[3])
        : "r"(a[0]), "r"(a[1]), "r"(a[2]), "r"(a[3]), "r"(b0), "r"(b1));
}

__device__ __forceinline__ void stage_sc(uint32_t sb, uint32_t bufbase,
                                         int m0, int n0, int k0, int tid) {
#pragma unroll
    for (int q = 0; q < 2; ++q) {
        int job = q * 256 + tid;
        int row = job >> 2, kg = job & 3;
        size_t src = (size_t)(m0 + row) * DD + k0 + kg * 8;
        uint32_t off = bufbase + (uint32_t)(row * ST_B + kg * 16);
        cp16(sb + SB_AHI + off, g_xhi + src);
        cp16(sb + SB_ALO + off, g_xlo + src);
    }
#pragma unroll
    for (int q = 0; q < 2; ++q) {
        int job = q * 256 + tid;
        int row = job >> 2, kg = job & 3;
        size_t src = (size_t)(n0 + row) * DD + k0 + kg * 8;
        uint32_t off = bufbase + (uint32_t)(row * ST_B + kg * 16);
        cp16(sb + SB_WHI + off, g_whi + src);
        cp16(sb + SB_WLO + off, g_wlo + src);
    }
}

__global__ __launch_bounds__(256) void xproj_mma_kernel(
    const float* __restrict__ bx,
    float* __restrict__ C)
{
    extern __shared__ char smem[];
    const uint32_t sb = smem_u32(smem);
    const int tid = threadIdx.x;
    const int wid = tid >> 5;
    const int l   = tid & 31;
    const int warp_m = wid & 3;
    const int warp_n = wid >> 2;
    const int m0 = blockIdx.x * 128;
    const int n0 = blockIdx.y * 128;

    float acc[2][8][4];
#pragma unroll
    for (int t = 0; t < 2; t++)
#pragma unroll
        for (int nb = 0; nb < 8; nb++)
#pragma unroll
            for (int i = 0; i < 4; i++) acc[t][nb][i] = 0.0f;

    const uint32_t aRowOff = (uint32_t)((warp_m * 32 + (l & 15)) * ST_B +
                                        (l >> 4) * 16);
    const uint32_t bRowOff = (uint32_t)((warp_n * 64 + ((l >> 4) << 3) + (l & 7)) * ST_B +
                                        ((l >> 3) & 1) * 16);

    stage_sc(sb, 0, m0, n0, 0, tid);
    CP_COMMIT();

#pragma unroll
    for (int sc = 0; sc < NSC; ++sc) {
        if (sc < NSC - 1) {
            stage_sc(sb, (uint32_t)(((sc + 1) & 1) * SB_BUF), m0, n0,
                     (sc + 1) * SC_K, tid);
            CP_COMMIT();
            cp_wait<1>();
        } else {
            cp_wait<0>();
        }
        __syncthreads();

        const uint32_t base = (uint32_t)((sc & 1) * SB_BUF);
#pragma unroll
        for (int ks = 0; ks < 2; ++ks) {
            const uint32_t kOff = (uint32_t)(ks * 32);
            uint32_t ahi[2][4], alo[2][4];
#pragma unroll
            for (int t = 0; t < 2; t++) {
                uint32_t abase = base + aRowOff + (uint32_t)(t * 16 * ST_B) + kOff;
                ldm_x4(ahi[t][0], ahi[t][1], ahi[t][2], ahi[t][3], sb + SB_AHI + abase);
                ldm_x4(alo[t][0], alo[t][1], alo[t][2], alo[t][3], sb + SB_ALO + abase);
            }
#pragma unroll
            for (int g = 0; g < 4; ++g) {
                uint32_t bbase = base + bRowOff + (uint32_t)(g * 16 * ST_B) + kOff;
                uint32_t h0, h1, h2, h3, q0, q1, q2, q3;
                ldm_x4(h0, h1, h2, h3, sb + SB_WHI + bbase);
                ldm_x4(q0, q1, q2, q3, sb + SB_WLO + bbase);
#pragma unroll
                for (int t = 0; t < 2; t++) {
                    mma16816(acc[t][2 * g],     ahi[t], h0, h1);
                    mma16816(acc[t][2 * g + 1], ahi[t], h2, h3);
                    mma16816(acc[t][2 * g],     alo[t], h0, h1);
                    mma16816(acc[t][2 * g + 1], alo[t], h2, h3);
                    mma16816(acc[t][2 * g],     ahi[t], q0, q1);
                    mma16816(acc[t][2 * g + 1], ahi[t], q2, q3);
                }
            }
        }
        __syncthreads();
    }

    const int mrow = m0 + warp_m * 32 + (l >> 2);
    const int ncol = n0 + warp_n * 64 + 2 * (l & 3);
#pragma unroll
    for (int t = 0; t < 2; t++) {
#pragma unroll
        for (int nb = 0; nb < 8; nb++) {
            int nn = ncol + nb * 8;
            float2 bv = *(const float2*)(bx + nn);
            int r0 = mrow + t * 16;
            float2 o0 = make_float2(acc[t][nb][0] + bv.x, acc[t][nb][1] + bv.y);
            float2 o1 = make_float2(acc[t][nb][2] + bv.x, acc[t][nb][3] + bv.y);
            *(float2*)(C + (size_t)r0 * HH + nn) = o0;
            *(float2*)(C + (size_t)(r0 + 8) * HH + nn) = o1;
        }
    }
}

// ====================================================================
// Kernel 2: scan v7 — 2-CTA cluster, ALL weights in registers.
//   Cluster c (2 CTAs) handles batches (2c, 2c+1).
//   CTA rank r owns output rows j in [r*128, r*128+128); per thread:
//   row j = r*128 + (tid>>2), k-quarter q = tid&3 (64 k-weights in regs).
//   Partials reduced via 2x shfl.xor; q0/q1 store local h + global out,
//   q2/q3 store the row to the partner CTA's smem (DSMEM).
//   One barrier.cluster per step. Zero smem weight traffic.
// ====================================================================
#define HSEG 72                      // padded 64-float k-segment
#define HB   (4 * HSEG)              // 288 floats per h vector

__global__ __launch_bounds__(512, 1) __cluster_dims__(2, 1, 1)
void scan_kernel(
    const float* __restrict__ h0,
    const float* __restrict__ Wh,
    const float* __restrict__ bh,
    float* __restrict__ out,
    int hasFinal)
{
    __shared__ float hbuf[2][2][HB];   // [ping][batch][4*72]

    const int tid  = threadIdx.x;
    const int q    = tid & 3;
    const int jloc = tid >> 2;         // 0..127
    uint32_t rank;
    asm("mov.u32 %0, %%cluster_ctarank;" : "=r"(rank));
    const int j   = (int)rank * 128 + jloc;
    const int cid = blockIdx.x >> 1;
    const int b0  = 2 * cid, b1 = 2 * cid + 1;

    // 64 k-weights in registers: k in [q*64, q*64+64)
    ulonglong2 wu[16];
    const ulonglong2* wrow = (const ulonglong2*)(Wh + (size_t)j * HH + q * 64);
#pragma unroll
    for (int i = 0; i < 16; i++) wu[i] = wrow[i];

    const float bh_r = bh[j];

    // load h0 for both batches into local smem (padded layout)
    {
        int bb = tid >> 8;             // 0/1
        int jj = tid & 255;
        int pos = (jj >> 6) * HSEG + (jj & 63);
        hbuf[0][bb][pos] = h0[(size_t)(bb ? b1 : b0) * HH + jj];
    }

    // remote (partner) smem base for hbuf
    uint32_t lbase = smem_u32(&hbuf[0][0][0]);
    uint32_t rbase;
    asm("mapa.shared::cluster.u32 %0, %1, %2;" : "=r"(rbase)
        : "r"(lbase), "r"(rank ^ 1u));

    // xp prefetch (q0 -> batch0, q1 -> batch1)
    const float* xpp = out + (size_t)((q & 1) ? b1 : b0) * HH + j;
    float xp_next = 0.0f;
    if (q < 2) xp_next = xpp[0];

    const int spos = (j >> 6) * HSEG + (j & 63);   // padded write slot for row j
    const int lane = tid & 31;
    const int lbaseq = lane & ~3;

    // partner must not receive step-0 remote stores before its smem is live;
    // also orders nothing else — one-time cost.
    asm volatile("barrier.cluster.arrive.aligned;" ::: "memory");
    asm volatile("barrier.cluster.wait.aligned;" ::: "memory");

    int cur = 0;
    for (int t = 0; t < LL; ++t) {
        const float xp = xp_next;
        if (q < 2 && t + 1 < LL) xp_next = xpp[(size_t)(t + 1) * SS];

        const ulonglong2* h0p = (const ulonglong2*)&hbuf[cur][0][q * HSEG];
        const ulonglong2* h1p = (const ulonglong2*)&hbuf[cur][1][q * HSEG];
        unsigned long long p00 = 0ULL, p01 = 0ULL, p10 = 0ULL, p11 = 0ULL;
#pragma unroll
        for (int i = 0; i < 16; i++) {
            ulonglong2 hv0 = h0p[i];
            ulonglong2 hv1 = h1p[i];
            p00 = ffma2(wu[i].x, hv0.x, p00);
            p01 = ffma2(wu[i].y, hv0.y, p01);
            p10 = ffma2(wu[i].x, hv1.x, p10);
            p11 = ffma2(wu[i].y, hv1.y, p11);
        }
        float d0 = upk_sum(p00) + upk_sum(p01);
        float d1 = upk_sum(p10) + upk_sum(p11);
        d0 += __shfl_xor_sync(0xFFFFFFFFu, d0, 1);
        d0 += __shfl_xor_sync(0xFFFFFFFFu, d0, 2);
        d1 += __shfl_xor_sync(0xFFFFFFFFu, d1, 1);
        d1 += __shfl_xor_sync(0xFFFFFFFFu, d1, 2);

        float hn = 0.0f;
        if (q < 2) {
            float v = ((q & 1) ? d1 : d0) + xp + bh_r;
            hn = tanhf(v);
        }
        const float hn0 = __shfl_sync(0xFFFFFFFFu, hn, lbaseq);
        const float hn1 = __shfl_sync(0xFFFFFFFFu, hn, lbaseq + 1);

        const int nxt = cur ^ 1;
        if (q == 0) {
            hbuf[nxt][0][spos] = hn0;
            out[(size_t)t * SS + (size_t)b0 * HH + j] = hn0;
            if (hasFinal && t == LL - 1)
                out[(size_t)LL * SS + (size_t)b0 * HH + j] = hn0;
        } else if (q == 1) {
            hbuf[nxt][1][spos] = hn1;
            out[(size_t)t * SS + (size_t)b1 * HH + j] = hn1;
            if (hasFinal && t == LL - 1)
                out[(size_t)LL * SS + (size_t)b1 * HH + j] = hn1;
        } else if (q == 2) {
            uint32_t ra = rbase + (uint32_t)(((nxt * 2 + 0) * HB + spos) * 4);
            asm volatile("st.shared::cluster.f32 [%0], %1;" :: "r"(ra), "f"(hn0) : "memory");
        } else {
            uint32_t ra = rbase + (uint32_t)(((nxt * 2 + 1) * HB + spos) * 4);
            asm volatile("st.shared::cluster.f32 [%0], %1;" :: "r"(ra), "f"(hn1) : "memory");
        }

        asm volatile("barrier.cluster.arrive.aligned;" ::: "memory");
        asm volatile("barrier.cluster.wait.aligned;" ::: "memory");
        cur = nxt;
    }
}

// ====================================================================
// launch
// ====================================================================
extern "C" void kernel_launch(void* const* d_in, const int* in_sizes, int n_in,
                              void* d_out, int out_size)
{
    const float* x   = (const float*)d_in[0];
    const float* h0  = (const float*)d_in[1];
    const float* Wxw = (const float*)d_in[2];
    const float* Wxb = (const float*)d_in[3];
    const float* Whw = (const float*)d_in[4];
    const float* Whb = (const float*)d_in[5];
    float* out = (float*)d_out;

    (void)in_sizes; (void)n_in;

    cudaFuncSetAttribute(xproj_mma_kernel, cudaFuncAttributeMaxDynamicSharedMemorySize, XP_SMEM);

    convert_kernel<<<(CV_JOBS + 255) / 256, 256>>>(x, Wxw);

    dim3 g1(LL * BB / 128, HH / 128);   // (1024, 2)
    xproj_mma_kernel<<<g1, 256, XP_SMEM>>>(Wxb, out);

    const int hasFinal = (out_size >= LL * BB * HH + BB * HH) ? 1 : 0;
    scan_kernel<<<BB, 512>>>(h0, Whw, Whb, out, hasFinal);
}

// round 15
// speedup vs baseline: 1.0356x; 1.0356x over previous
#include <cuda_runtime.h>
#include <cuda_bf16.h>
#include <math.h>
#include <stdint.h>

#define LL 1024
#define BB 128
#define DD 256
#define HH 256
#define SS (BB * HH)

#define XN (LL * BB * DD)
#define WN (HH * DD)

// Pre-split bf16 scratch (static device arrays — allowed)
__device__ __align__(16) __nv_bfloat16 g_xhi[XN];
__device__ __align__(16) __nv_bfloat16 g_xlo[XN];
__device__ __align__(16) __nv_bfloat16 g_whi[WN];
__device__ __align__(16) __nv_bfloat16 g_wlo[WN];

__device__ __forceinline__ uint32_t smem_u32(const void* p) {
    uint32_t a;
    asm("{ .reg .u64 t; cvta.to.shared.u64 t, %1; cvt.u32.u64 %0, t; }"
        : "=r"(a) : "l"(p));
    return a;
}

// Packed f32x2 FMA
__device__ __forceinline__ unsigned long long ffma2(
    unsigned long long a, unsigned long long b, unsigned long long c)
{
    unsigned long long d;
    asm("fma.rn.f32x2 %0, %1, %2, %3;" : "=l"(d) : "l"(a), "l"(b), "l"(c));
    return d;
}
__device__ __forceinline__ float upk_sum(unsigned long long p)
{
    float lo, hi;
    asm("mov.b64 {%0, %1}, %2;" : "=f"(lo), "=f"(hi) : "l"(p));
    return lo + hi;
}

// fast tanh: 1 - 2/(e^{2x}+1); exact at saturations, rel err ~1e-6
__device__ __forceinline__ float fast_tanh(float x)
{
    float e = __expf(x + x);
    float r;
    asm("rcp.approx.f32 %0, %1;" : "=f"(r) : "f"(e + 1.0f));
    return fmaf(-2.0f, r, 1.0f);
}

__device__ __forceinline__ void split2(float a, float b, uint32_t& h, uint32_t& l) {
    __nv_bfloat16 ha = __float2bfloat16(a);
    __nv_bfloat16 hb = __float2bfloat16(b);
    float ra = a - __bfloat162float(ha);
    float rb = b - __bfloat162float(hb);
    __nv_bfloat16 la = __float2bfloat16(ra);
    __nv_bfloat16 lb = __float2bfloat16(rb);
    h = (uint32_t)reinterpret_cast<unsigned short&>(ha) |
        ((uint32_t)reinterpret_cast<unsigned short&>(hb) << 16);
    l = (uint32_t)reinterpret_cast<unsigned short&>(la) |
        ((uint32_t)reinterpret_cast<unsigned short&>(lb) << 16);
}

// cp.async helpers
__device__ __forceinline__ void cp16(uint32_t s, const void* g) {
    asm volatile("cp.async.cg.shared.global [%0], [%1], 16;" :: "r"(s), "l"(g));
}
#define CP_COMMIT() asm volatile("cp.async.commit_group;" ::: "memory")
template <int N>
__device__ __forceinline__ void cp_wait() {
    asm volatile("cp.async.wait_group %0;" :: "n"(N) : "memory");
}

// ====================================================================
// Kernel 0: one-shot fp32 -> split-bf16 (hi, lo) for X and Wx.
// ====================================================================
#define CV_JOBS ((XN + WN) / 4)

__global__ __launch_bounds__(256) void convert_kernel(
    const float* __restrict__ X, const float* __restrict__ Wx)
{
    int i = blockIdx.x * 256 + threadIdx.x;
    if (i >= CV_JOBS) return;
    float4 v;
    if (i < XN / 4) v = ((const float4*)X)[i];
    else            v = ((const float4*)Wx)[i - XN / 4];
    uint2 hi, lo;
    split2(v.x, v.y, hi.x, lo.x);
    split2(v.z, v.w, hi.y, lo.y);
    if (i < XN / 4) {
        *(uint2*)(g_xhi + (size_t)i * 4) = hi;
        *(uint2*)(g_xlo + (size_t)i * 4) = lo;
    } else {
        size_t o = (size_t)(i - XN / 4) * 4;
        *(uint2*)(g_whi + o) = hi;
        *(uint2*)(g_wlo + o) = lo;
    }
}

// ====================================================================
// Kernel 1: xproj GEMM — R13 pipeline, grid order swapped so the two
// n-tiles of one m-tile are adjacent CTAs (X re-read hits L2).
// ====================================================================
#define SC_K   32
#define NSC    8
#define ST_B   80
#define ST_TILE (128 * ST_B)
#define SB_AHI 0
#define SB_ALO ST_TILE
#define SB_WHI (2 * ST_TILE)
#define SB_WLO (3 * ST_TILE)
#define SB_BUF (4 * ST_TILE)
#define XP_SMEM (2 * SB_BUF)

__device__ __forceinline__ void ldm_x4(uint32_t& r0, uint32_t& r1,
                                       uint32_t& r2, uint32_t& r3, uint32_t addr) {
    asm volatile("ldmatrix.sync.aligned.m8n8.x4.shared.b16 {%0,%1,%2,%3}, [%4];"
                 : "=r"(r0), "=r"(r1), "=r"(r2), "=r"(r3) : "r"(addr));
}

__device__ __forceinline__ void mma16816(float* c, const uint32_t* a,
                                         uint32_t b0, uint32_t b1) {
    asm volatile(
        "mma.sync.aligned.m16n8k16.row.col.f32.bf16.bf16.f32 "
        "{%0,%1,%2,%3}, {%4,%5,%6,%7}, {%8,%9}, {%0,%1,%2,%3};"
        : "+f"(c[0]), "+f"(c[1]), "+f"(c[2]), "+f"(c[3])
        : "r"(a[0]), "r"(a[1]), "r"(a[2]), "r"(a[3]), "r"(b0), "r"(b1));
}

__device__ __forceinline__ void stage_sc(uint32_t sb, uint32_t bufbase,
                                         int m0, int n0, int k0, int tid) {
#pragma unroll
    for (int q = 0; q < 2; ++q) {
        int job = q * 256 + tid;
        int row = job >> 2, kg = job & 3;
        size_t src = (size_t)(m0 + row) * DD + k0 + kg * 8;
        uint32_t off = bufbase + (uint32_t)(row * ST_B + kg * 16);
        cp16(sb + SB_AHI + off, g_xhi + src);
        cp16(sb + SB_ALO + off, g_xlo + src);
    }
#pragma unroll
    for (int q = 0; q < 2; ++q) {
        int job = q * 256 + tid;
        int row = job >> 2, kg = job & 3;
        size_t src = (size_t)(n0 + row) * DD + k0 + kg * 8;
        uint32_t off = bufbase + (uint32_t)(row * ST_B + kg * 16);
        cp16(sb + SB_WHI + off, g_whi + src);
        cp16(sb + SB_WLO + off, g_wlo + src);
    }
}

__global__ __launch_bounds__(256) void xproj_mma_kernel(
    const float* __restrict__ bx,
    float* __restrict__ C)
{
    extern __shared__ char smem[];
    const uint32_t sb = smem_u32(smem);
    const int tid = threadIdx.x;
    const int wid = tid >> 5;
    const int l   = tid & 31;
    const int warp_m = wid & 3;
    const int warp_n = wid >> 2;
    const int m0 = blockIdx.y * 128;    // swapped: y = m-tile
    const int n0 = blockIdx.x * 128;    // swapped: x = n-tile (2 per m, adjacent)

    float acc[2][8][4];
#pragma unroll
    for (int t = 0; t < 2; t++)
#pragma unroll
        for (int nb = 0; nb < 8; nb++)
#pragma unroll
            for (int i = 0; i < 4; i++) acc[t][nb][i] = 0.0f;

    const uint32_t aRowOff = (uint32_t)((warp_m * 32 + (l & 15)) * ST_B +
                                        (l >> 4) * 16);
    const uint32_t bRowOff = (uint32_t)((warp_n * 64 + ((l >> 4) << 3) + (l & 7)) * ST_B +
                                        ((l >> 3) & 1) * 16);

    stage_sc(sb, 0, m0, n0, 0, tid);
    CP_COMMIT();

#pragma unroll
    for (int sc = 0; sc < NSC; ++sc) {
        if (sc < NSC - 1) {
            stage_sc(sb, (uint32_t)(((sc + 1) & 1) * SB_BUF), m0, n0,
                     (sc + 1) * SC_K, tid);
            CP_COMMIT();
            cp_wait<1>();
        } else {
            cp_wait<0>();
        }
        __syncthreads();

        const uint32_t base = (uint32_t)((sc & 1) * SB_BUF);
#pragma unroll
        for (int ks = 0; ks < 2; ++ks) {
            const uint32_t kOff = (uint32_t)(ks * 32);
            uint32_t ahi[2][4], alo[2][4];
#pragma unroll
            for (int t = 0; t < 2; t++) {
                uint32_t abase = base + aRowOff + (uint32_t)(t * 16 * ST_B) + kOff;
                ldm_x4(ahi[t][0], ahi[t][1], ahi[t][2], ahi[t][3], sb + SB_AHI + abase);
                ldm_x4(alo[t][0], alo[t][1], alo[t][2], alo[t][3], sb + SB_ALO + abase);
            }
#pragma unroll
            for (int g = 0; g < 4; ++g) {
                uint32_t bbase = base + bRowOff + (uint32_t)(g * 16 * ST_B) + kOff;
                uint32_t h0, h1, h2, h3, q0, q1, q2, q3;
                ldm_x4(h0, h1, h2, h3, sb + SB_WHI + bbase);
                ldm_x4(q0, q1, q2, q3, sb + SB_WLO + bbase);
#pragma unroll
                for (int t = 0; t < 2; t++) {
                    mma16816(acc[t][2 * g],     ahi[t], h0, h1);
                    mma16816(acc[t][2 * g + 1], ahi[t], h2, h3);
                    mma16816(acc[t][2 * g],     alo[t], h0, h1);
                    mma16816(acc[t][2 * g + 1], alo[t], h2, h3);
                    mma16816(acc[t][2 * g],     ahi[t], q0, q1);
                    mma16816(acc[t][2 * g + 1], ahi[t], q2, q3);
                }
            }
        }
        __syncthreads();
    }

    const int mrow = m0 + warp_m * 32 + (l >> 2);
    const int ncol = n0 + warp_n * 64 + 2 * (l & 3);
#pragma unroll
    for (int t = 0; t < 2; t++) {
#pragma unroll
        for (int nb = 0; nb < 8; nb++) {
            int nn = ncol + nb * 8;
            float2 bv = *(const float2*)(bx + nn);
            int r0 = mrow + t * 16;
            float2 o0 = make_float2(acc[t][nb][0] + bv.x, acc[t][nb][1] + bv.y);
            float2 o1 = make_float2(acc[t][nb][2] + bv.x, acc[t][nb][3] + bv.y);
            *(float2*)(C + (size_t)r0 * HH + nn) = o0;
            *(float2*)(C + (size_t)(r0 + 8) * HH + nn) = o1;
        }
    }
}

// ====================================================================
// Kernel 2: scan — R10/R13 structure (lane-paired halves, shuffle
// combine, 1 barrier/step, padded hbuf) + fast exp-based tanh.
// ====================================================================
#define HPAD 264   // 128 + 8 + 128 floats per h snapshot

__global__ __launch_bounds__(512, 1) void scan_kernel(
    const float* __restrict__ h0,
    const float* __restrict__ Wh,
    const float* __restrict__ bh,
    float* __restrict__ out,
    int hasFinal)
{
    extern __shared__ float smemf[];
    float4* Wsm  = (float4*)smemf;           // [8][512] float4 = 64 KB
    float*  hbuf = smemf + 8 * 512 * 4;      // 2 * HPAD floats (ping-pong)

    const int tid  = threadIdx.x;
    const int j    = tid >> 1;
    const int half = tid & 1;
    const int b    = blockIdx.x;
    const int kb   = half * 128;

    ulonglong2 wu[24];
    const ulonglong2* wrow = (const ulonglong2*)(Wh + (size_t)j * HH + kb);
#pragma unroll
    for (int i = 0; i < 24; i++) wu[i] = wrow[i];

    const float4* wrow4 = (const float4*)(Wh + (size_t)j * HH + kb);
#pragma unroll
    for (int g = 0; g < 8; ++g)
        Wsm[g * 512 + tid] = wrow4[24 + g];

    if (tid < 256) {
        int pos = tid + ((tid >> 7) << 3);   // +8 pad for upper half
        hbuf[pos] = h0[(size_t)b * HH + tid];
    }
    const float bh_r = bh[j];
    float* const outp = out + (size_t)b * HH + j;   // step stride SS

    float xp_next = outp[0];
    __syncthreads();

    const int hpos = j + ((j >> 7) << 3);
    int cur = 0;
    for (int t = 0; t < LL; ++t) {
        const float xp = xp_next;
        if (t + 1 < LL) xp_next = outp[(size_t)(t + 1) * SS];

        const ulonglong2* h2 = (const ulonglong2*)(hbuf + cur * HPAD + half * 136);
        unsigned long long p0 = 0ULL, p1 = 0ULL, p2 = 0ULL, p3 = 0ULL;
#pragma unroll
        for (int i = 0; i < 24; i++) {
            ulonglong2 hv = h2[i];
            p0 = ffma2(wu[i].x, hv.x, p0);
            p1 = ffma2(wu[i].y, hv.y, p1);
        }
        const ulonglong2* ws2 = (const ulonglong2*)Wsm;
#pragma unroll
        for (int g = 0; g < 8; g++) {
            ulonglong2 wv = ws2[(size_t)g * 512 + tid];
            ulonglong2 hv = h2[24 + g];
            p2 = ffma2(wv.x, hv.x, p2);
            p3 = ffma2(wv.y, hv.y, p3);
        }
        float acc = (upk_sum(p0) + upk_sum(p1)) + (upk_sum(p2) + upk_sum(p3));
        float other = __shfl_xor_sync(0xFFFFFFFFu, acc, 1);
        float hn = fast_tanh(acc + other + xp + bh_r);

        if (!half) {
            hbuf[(cur ^ 1) * HPAD + hpos] = hn;
        } else {
            outp[(size_t)t * SS] = hn;
            if (hasFinal && t == LL - 1)
                outp[(size_t)LL * SS] = hn;
        }
        __syncthreads();
        cur ^= 1;
    }
}

// ====================================================================
// launch
// ====================================================================
extern "C" void kernel_launch(void* const* d_in, const int* in_sizes, int n_in,
                              void* d_out, int out_size)
{
    const float* x   = (const float*)d_in[0];
    const float* h0  = (const float*)d_in[1];
    const float* Wxw = (const float*)d_in[2];
    const float* Wxb = (const float*)d_in[3];
    const float* Whw = (const float*)d_in[4];
    const float* Whb = (const float*)d_in[5];
    float* out = (float*)d_out;

    (void)in_sizes; (void)n_in;

    cudaFuncSetAttribute(xproj_mma_kernel, cudaFuncAttributeMaxDynamicSharedMemorySize, XP_SMEM);
    const int smemScan = (8 * 512 * 4 + 2 * HPAD) * (int)sizeof(float);
    cudaFuncSetAttribute(scan_kernel, cudaFuncAttributeMaxDynamicSharedMemorySize, smemScan);

    convert_kernel<<<(CV_JOBS + 255) / 256, 256>>>(x, Wxw);

    dim3 g1(HH / 128, LL * BB / 128);   // (2, 1024): n-tiles adjacent per m-tile
    xproj_mma_kernel<<<g1, 256, XP_SMEM>>>(Wxb, out);

    const int hasFinal = (out_size >= LL * BB * HH + BB * HH) ? 1 : 0;
    scan_kernel<<<BB, 512, smemScan>>>(h0, Whw, Whb, out, hasFinal);
}

// round 16
// speedup vs baseline: 1.7920x; 1.7304x over previous
#include <cuda_runtime.h>
#include <cuda_bf16.h>
#include <math.h>
#include <stdint.h>

#define LL 1024
#define BB 128
#define DD 256
#define HH 256
#define SS (BB * HH)

#define XN (LL * BB * DD)
#define WN (HH * DD)

// Pre-split bf16 scratch (static device arrays — allowed)
__device__ __align__(16) __nv_bfloat16 g_xhi[XN];
__device__ __align__(16) __nv_bfloat16 g_xlo[XN];
__device__ __align__(16) __nv_bfloat16 g_whi[WN];
__device__ __align__(16) __nv_bfloat16 g_wlo[WN];

__device__ __forceinline__ uint32_t smem_u32(const void* p) {
    uint32_t a;
    asm("{ .reg .u64 t; cvta.to.shared.u64 t, %1; cvt.u32.u64 %0, t; }"
        : "=r"(a) : "l"(p));
    return a;
}

// Packed f32x2 FMA
__device__ __forceinline__ unsigned long long ffma2(
    unsigned long long a, unsigned long long b, unsigned long long c)
{
    unsigned long long d;
    asm("fma.rn.f32x2 %0, %1, %2, %3;" : "=l"(d) : "l"(a), "l"(b), "l"(c));
    return d;
}
__device__ __forceinline__ float upk_sum(unsigned long long p)
{
    float lo, hi;
    asm("mov.b64 {%0, %1}, %2;" : "=f"(lo), "=f"(hi) : "l"(p));
    return lo + hi;
}

__device__ __forceinline__ void split2(float a, float b, uint32_t& h, uint32_t& l) {
    __nv_bfloat16 ha = __float2bfloat16(a);
    __nv_bfloat16 hb = __float2bfloat16(b);
    float ra = a - __bfloat162float(ha);
    float rb = b - __bfloat162float(hb);
    __nv_bfloat16 la = __float2bfloat16(ra);
    __nv_bfloat16 lb = __float2bfloat16(rb);
    h = (uint32_t)reinterpret_cast<unsigned short&>(ha) |
        ((uint32_t)reinterpret_cast<unsigned short&>(hb) << 16);
    l = (uint32_t)reinterpret_cast<unsigned short&>(la) |
        ((uint32_t)reinterpret_cast<unsigned short&>(lb) << 16);
}

// cp.async helpers
__device__ __forceinline__ void cp16(uint32_t s, const void* g) {
    asm volatile("cp.async.cg.shared.global [%0], [%1], 16;" :: "r"(s), "l"(g));
}
#define CP_COMMIT() asm volatile("cp.async.commit_group;" ::: "memory")
template <int N>
__device__ __forceinline__ void cp_wait() {
    asm volatile("cp.async.wait_group %0;" :: "n"(N) : "memory");
}

// ====================================================================
// Kernel 0: one-shot fp32 -> split-bf16 (hi, lo) for X and Wx.
// ====================================================================
#define CV_JOBS ((XN + WN) / 4)

__global__ __launch_bounds__(256) void convert_kernel(
    const float* __restrict__ X, const float* __restrict__ Wx)
{
    int i = blockIdx.x * 256 + threadIdx.x;
    if (i >= CV_JOBS) return;
    float4 v;
    if (i < XN / 4) v = ((const float4*)X)[i];
    else            v = ((const float4*)Wx)[i - XN / 4];
    uint2 hi, lo;
    split2(v.x, v.y, hi.x, lo.x);
    split2(v.z, v.w, hi.y, lo.y);
    if (i < XN / 4) {
        *(uint2*)(g_xhi + (size_t)i * 4) = hi;
        *(uint2*)(g_xlo + (size_t)i * 4) = lo;
    } else {
        size_t o = (size_t)(i - XN / 4) * 4;
        *(uint2*)(g_whi + o) = hi;
        *(uint2*)(g_wlo + o) = lo;
    }
}

// ====================================================================
// Kernel 1: xproj GEMM (exact R13 version — best measured).
// Sub-chunk double-buffered cp.async pipeline, mma.sync bf16 split-3.
// ====================================================================
#define SC_K   32
#define NSC    8
#define ST_B   80
#define ST_TILE (128 * ST_B)
#define SB_AHI 0
#define SB_ALO ST_TILE
#define SB_WHI (2 * ST_TILE)
#define SB_WLO (3 * ST_TILE)
#define SB_BUF (4 * ST_TILE)
#define XP_SMEM (2 * SB_BUF)

__device__ __forceinline__ void ldm_x4(uint32_t& r0, uint32_t& r1,
                                       uint32_t& r2, uint32_t& r3, uint32_t addr) {
    asm volatile("ldmatrix.sync.aligned.m8n8.x4.shared.b16 {%0,%1,%2,%3}, [%4];"
                 : "=r"(r0), "=r"(r1), "=r"(r2), "=r"(r3) : "r"(addr));
}

__device__ __forceinline__ void mma16816(float* c, const uint32_t* a,
                                         uint32_t b0, uint32_t b1) {
    asm volatile(
        "mma.sync.aligned.m16n8k16.row.col.f32.bf16.bf16.f32 "
        "{%0,%1,%2,%3}, {%4,%5,%6,%7}, {%8,%9}, {%0,%1,%2,%3};"
        : "+f"(c[0]), "+f"(c[1]), "+f"(c[2]), "+f"(c[3])
        : "r"(a[0]), "r"(a[1]), "r"(a[2]), "r"(a[3]), "r"(b0), "r"(b1));
}

__device__ __forceinline__ void stage_sc(uint32_t sb, uint32_t bufbase,
                                         int m0, int n0, int k0, int tid) {
#pragma unroll
    for (int q = 0; q < 2; ++q) {
        int job = q * 256 + tid;
        int row = job >> 2, kg = job & 3;
        size_t src = (size_t)(m0 + row) * DD + k0 + kg * 8;
        uint32_t off = bufbase + (uint32_t)(row * ST_B + kg * 16);
        cp16(sb + SB_AHI + off, g_xhi + src);
        cp16(sb + SB_ALO + off, g_xlo + src);
    }
#pragma unroll
    for (int q = 0; q < 2; ++q) {
        int job = q * 256 + tid;
        int row = job >> 2, kg = job & 3;
        size_t src = (size_t)(n0 + row) * DD + k0 + kg * 8;
        uint32_t off = bufbase + (uint32_t)(row * ST_B + kg * 16);
        cp16(sb + SB_WHI + off, g_whi + src);
        cp16(sb + SB_WLO + off, g_wlo + src);
    }
}

__global__ __launch_bounds__(256) void xproj_mma_kernel(
    const float* __restrict__ bx,
    float* __restrict__ C)
{
    extern __shared__ char smem[];
    const uint32_t sb = smem_u32(smem);
    const int tid = threadIdx.x;
    const int wid = tid >> 5;
    const int l   = tid & 31;
    const int warp_m = wid & 3;
    const int warp_n = wid >> 2;
    const int m0 = blockIdx.x * 128;
    const int n0 = blockIdx.y * 128;

    float acc[2][8][4];
#pragma unroll
    for (int t = 0; t < 2; t++)
#pragma unroll
        for (int nb = 0; nb < 8; nb++)
#pragma unroll
            for (int i = 0; i < 4; i++) acc[t][nb][i] = 0.0f;

    const uint32_t aRowOff = (uint32_t)((warp_m * 32 + (l & 15)) * ST_B +
                                        (l >> 4) * 16);
    const uint32_t bRowOff = (uint32_t)((warp_n * 64 + ((l >> 4) << 3) + (l & 7)) * ST_B +
                                        ((l >> 3) & 1) * 16);

    stage_sc(sb, 0, m0, n0, 0, tid);
    CP_COMMIT();

#pragma unroll
    for (int sc = 0; sc < NSC; ++sc) {
        if (sc < NSC - 1) {
            stage_sc(sb, (uint32_t)(((sc + 1) & 1) * SB_BUF), m0, n0,
                     (sc + 1) * SC_K, tid);
            CP_COMMIT();
            cp_wait<1>();
        } else {
            cp_wait<0>();
        }
        __syncthreads();

        const uint32_t base = (uint32_t)((sc & 1) * SB_BUF);
#pragma unroll
        for (int ks = 0; ks < 2; ++ks) {
            const uint32_t kOff = (uint32_t)(ks * 32);
            uint32_t ahi[2][4], alo[2][4];
#pragma unroll
            for (int t = 0; t < 2; t++) {
                uint32_t abase = base + aRowOff + (uint32_t)(t * 16 * ST_B) + kOff;
                ldm_x4(ahi[t][0], ahi[t][1], ahi[t][2], ahi[t][3], sb + SB_AHI + abase);
                ldm_x4(alo[t][0], alo[t][1], alo[t][2], alo[t][3], sb + SB_ALO + abase);
            }
#pragma unroll
            for (int g = 0; g < 4; ++g) {
                uint32_t bbase = base + bRowOff + (uint32_t)(g * 16 * ST_B) + kOff;
                uint32_t h0, h1, h2, h3, q0, q1, q2, q3;
                ldm_x4(h0, h1, h2, h3, sb + SB_WHI + bbase);
                ldm_x4(q0, q1, q2, q3, sb + SB_WLO + bbase);
#pragma unroll
                for (int t = 0; t < 2; t++) {
                    mma16816(acc[t][2 * g],     ahi[t], h0, h1);
                    mma16816(acc[t][2 * g + 1], ahi[t], h2, h3);
                    mma16816(acc[t][2 * g],     alo[t], h0, h1);
                    mma16816(acc[t][2 * g + 1], alo[t], h2, h3);
                    mma16816(acc[t][2 * g],     ahi[t], q0, q1);
                    mma16816(acc[t][2 * g + 1], ahi[t], q2, q3);
                }
            }
        }
        __syncthreads();
    }

    const int mrow = m0 + warp_m * 32 + (l >> 2);
    const int ncol = n0 + warp_n * 64 + 2 * (l & 3);
#pragma unroll
    for (int t = 0; t < 2; t++) {
#pragma unroll
        for (int nb = 0; nb < 8; nb++) {
            int nn = ncol + nb * 8;
            float2 bv = *(const float2*)(bx + nn);
            int r0 = mrow + t * 16;
            float2 o0 = make_float2(acc[t][nb][0] + bv.x, acc[t][nb][1] + bv.y);
            float2 o1 = make_float2(acc[t][nb][2] + bv.x, acc[t][nb][3] + bv.y);
            *(float2*)(C + (size_t)r0 * HH + nn) = o0;
            *(float2*)(C + (size_t)(r0 + 8) * HH + nn) = o1;
        }
    }
}

// ====================================================================
// Kernel 2: scan (R10/R13 structure — lane-paired halves, shuffle
// combine, 1 barrier/step, padded hbuf, tanhf). Final-state store
// hoisted out of the loop (only per-step delta vs R13).
// ====================================================================
#define HPAD 264   // 128 + 8 + 128 floats per h snapshot

__global__ __launch_bounds__(512, 1) void scan_kernel(
    const float* __restrict__ h0,
    const float* __restrict__ Wh,
    const float* __restrict__ bh,
    float* __restrict__ out,
    int hasFinal)
{
    extern __shared__ float smemf[];
    float4* Wsm  = (float4*)smemf;           // [8][512] float4 = 64 KB
    float*  hbuf = smemf + 8 * 512 * 4;      // 2 * HPAD floats (ping-pong)

    const int tid  = threadIdx.x;
    const int j    = tid >> 1;
    const int half = tid & 1;
    const int b    = blockIdx.x;
    const int kb   = half * 128;

    ulonglong2 wu[24];
    const ulonglong2* wrow = (const ulonglong2*)(Wh + (size_t)j * HH + kb);
#pragma unroll
    for (int i = 0; i < 24; i++) wu[i] = wrow[i];

    const float4* wrow4 = (const float4*)(Wh + (size_t)j * HH + kb);
#pragma unroll
    for (int g = 0; g < 8; ++g)
        Wsm[g * 512 + tid] = wrow4[24 + g];

    if (tid < 256) {
        int pos = tid + ((tid >> 7) << 3);   // +8 pad for upper half
        hbuf[pos] = h0[(size_t)b * HH + tid];
    }
    const float bh_r = bh[j];
    float* const outp = out + (size_t)b * HH + j;   // step stride SS

    float xp_next = outp[0];
    __syncthreads();

    const int hpos = j + ((j >> 7) << 3);
    int cur = 0;
    for (int t = 0; t < LL; ++t) {
        const float xp = xp_next;
        if (t + 1 < LL) xp_next = outp[(size_t)(t + 1) * SS];

        const ulonglong2* h2 = (const ulonglong2*)(hbuf + cur * HPAD + half * 136);
        unsigned long long p0 = 0ULL, p1 = 0ULL, p2 = 0ULL, p3 = 0ULL;
#pragma unroll
        for (int i = 0; i < 24; i++) {
            ulonglong2 hv = h2[i];
            p0 = ffma2(wu[i].x, hv.x, p0);
            p1 = ffma2(wu[i].y, hv.y, p1);
        }
        const ulonglong2* ws2 = (const ulonglong2*)Wsm;
#pragma unroll
        for (int g = 0; g < 8; g++) {
            ulonglong2 wv = ws2[(size_t)g * 512 + tid];
            ulonglong2 hv = h2[24 + g];
            p2 = ffma2(wv.x, hv.x, p2);
            p3 = ffma2(wv.y, hv.y, p3);
        }
        float acc = (upk_sum(p0) + upk_sum(p1)) + (upk_sum(p2) + upk_sum(p3));
        float other = __shfl_xor_sync(0xFFFFFFFFu, acc, 1);
        float hn = tanhf(acc + other + xp + bh_r);

        if (!half) {
            hbuf[(cur ^ 1) * HPAD + hpos] = hn;
        } else {
            outp[(size_t)t * SS] = hn;
        }
        __syncthreads();
        cur ^= 1;
    }

    // final state h_L (hoisted out of the loop): re-read the value the
    // half==1 thread just wrote for t = LL-1 and copy it to the tail slot.
    if (hasFinal && half) {
        outp[(size_t)LL * SS] = outp[(size_t)(LL - 1) * SS];
    }
}

// ====================================================================
// launch
// ====================================================================
extern "C" void kernel_launch(void* const* d_in, const int* in_sizes, int n_in,
                              void* d_out, int out_size)
{
    const float* x   = (const float*)d_in[0];
    const float* h0  = (const float*)d_in[1];
    const float* Wxw = (const float*)d_in[2];
    const float* Wxb = (const float*)d_in[3];
    const float* Whw = (const float*)d_in[4];
    const float* Whb = (const float*)d_in[5];
    float* out = (float*)d_out;

    (void)in_sizes; (void)n_in;

    cudaFuncSetAttribute(xproj_mma_kernel, cudaFuncAttributeMaxDynamicSharedMemorySize, XP_SMEM);
    const int smemScan = (8 * 512 * 4 + 2 * HPAD) * (int)sizeof(float);
    cudaFuncSetAttribute(scan_kernel, cudaFuncAttributeMaxDynamicSharedMemorySize, smemScan);

    convert_kernel<<<(CV_JOBS + 255) / 256, 256>>>(x, Wxw);

    dim3 g1(LL * BB / 128, HH / 128);   // (1024, 2) — R13 order, known good
    xproj_mma_kernel<<<g1, 256, XP_SMEM>>>(Wxb, out);

    const int hasFinal = (out_size >= LL * BB * HH + BB * HH) ? 1 : 0;
    scan_kernel<<<BB, 512, smemScan>>>(h0, Whw, Whb, out, hasFinal);
}

// round 17
// speedup vs baseline: 1.8359x; 1.0245x over previous
#include <cuda_runtime.h>
#include <cuda_bf16.h>
#include <math.h>
#include <stdint.h>

#define LL 1024
#define BB 128
#define DD 256
#define HH 256
#define SS (BB * HH)

#define XN (LL * BB * DD)
#define WN (HH * DD)

// Pre-split bf16 scratch (static device arrays — allowed)
__device__ __align__(16) __nv_bfloat16 g_xhi[XN];
__device__ __align__(16) __nv_bfloat16 g_xlo[XN];
__device__ __align__(16) __nv_bfloat16 g_whi[WN];
__device__ __align__(16) __nv_bfloat16 g_wlo[WN];

__device__ __forceinline__ uint32_t smem_u32(const void* p) {
    uint32_t a;
    asm("{ .reg .u64 t; cvta.to.shared.u64 t, %1; cvt.u32.u64 %0, t; }"
        : "=r"(a) : "l"(p));
    return a;
}

// Packed f32x2 FMA
__device__ __forceinline__ unsigned long long ffma2(
    unsigned long long a, unsigned long long b, unsigned long long c)
{
    unsigned long long d;
    asm("fma.rn.f32x2 %0, %1, %2, %3;" : "=l"(d) : "l"(a), "l"(b), "l"(c));
    return d;
}
__device__ __forceinline__ float upk_sum(unsigned long long p)
{
    float lo, hi;
    asm("mov.b64 {%0, %1}, %2;" : "=f"(lo), "=f"(hi) : "l"(p));
    return lo + hi;
}

__device__ __forceinline__ void split2(float a, float b, uint32_t& h, uint32_t& l) {
    __nv_bfloat16 ha = __float2bfloat16(a);
    __nv_bfloat16 hb = __float2bfloat16(b);
    float ra = a - __bfloat162float(ha);
    float rb = b - __bfloat162float(hb);
    __nv_bfloat16 la = __float2bfloat16(ra);
    __nv_bfloat16 lb = __float2bfloat16(rb);
    h = (uint32_t)reinterpret_cast<unsigned short&>(ha) |
        ((uint32_t)reinterpret_cast<unsigned short&>(hb) << 16);
    l = (uint32_t)reinterpret_cast<unsigned short&>(la) |
        ((uint32_t)reinterpret_cast<unsigned short&>(lb) << 16);
}

// cp.async helpers
__device__ __forceinline__ void cp16(uint32_t s, const void* g) {
    asm volatile("cp.async.cg.shared.global [%0], [%1], 16;" :: "r"(s), "l"(g));
}
#define CP_COMMIT() asm volatile("cp.async.commit_group;" ::: "memory")
template <int N>
__device__ __forceinline__ void cp_wait() {
    asm volatile("cp.async.wait_group %0;" :: "n"(N) : "memory");
}

// ====================================================================
// Kernel 0: one-shot fp32 -> split-bf16 (hi, lo) for X and Wx.
// ====================================================================
#define CV_JOBS ((XN + WN) / 4)

__global__ __launch_bounds__(256) void convert_kernel(
    const float* __restrict__ X, const float* __restrict__ Wx)
{
    int i = blockIdx.x * 256 + threadIdx.x;
    if (i >= CV_JOBS) return;
    float4 v;
    if (i < XN / 4) v = ((const float4*)X)[i];
    else            v = ((const float4*)Wx)[i - XN / 4];
    uint2 hi, lo;
    split2(v.x, v.y, hi.x, lo.x);
    split2(v.z, v.w, hi.y, lo.y);
    if (i < XN / 4) {
        *(uint2*)(g_xhi + (size_t)i * 4) = hi;
        *(uint2*)(g_xlo + (size_t)i * 4) = lo;
    } else {
        size_t o = (size_t)(i - XN / 4) * 4;
        *(uint2*)(g_whi + o) = hi;
        *(uint2*)(g_wlo + o) = lo;
    }
}

// ====================================================================
// Kernel 1: xproj GEMM (exact R13/R16 version — best measured).
// Sub-chunk double-buffered cp.async pipeline, mma.sync bf16 split-3.
// ====================================================================
#define SC_K   32
#define NSC    8
#define ST_B   80
#define ST_TILE (128 * ST_B)
#define SB_AHI 0
#define SB_ALO ST_TILE
#define SB_WHI (2 * ST_TILE)
#define SB_WLO (3 * ST_TILE)
#define SB_BUF (4 * ST_TILE)
#define XP_SMEM (2 * SB_BUF)

__device__ __forceinline__ void ldm_x4(uint32_t& r0, uint32_t& r1,
                                       uint32_t& r2, uint32_t& r3, uint32_t addr) {
    asm volatile("ldmatrix.sync.aligned.m8n8.x4.shared.b16 {%0,%1,%2,%3}, [%4];"
                 : "=r"(r0), "=r"(r1), "=r"(r2), "=r"(r3) : "r"(addr));
}

__device__ __forceinline__ void mma16816(float* c, const uint32_t* a,
                                         uint32_t b0, uint32_t b1) {
    asm volatile(
        "mma.sync.aligned.m16n8k16.row.col.f32.bf16.bf16.f32 "
        "{%0,%1,%2,%3}, {%4,%5,%6,%7}, {%8,%9}, {%0,%1,%2,%3};"
        : "+f"(c[0]), "+f"(c[1]), "+f"(c[2]), "+f"(c[3])
        : "r"(a[0]), "r"(a[1]), "r"(a[2]), "r"(a[3]), "r"(b0), "r"(b1));
}

__device__ __forceinline__ void stage_sc(uint32_t sb, uint32_t bufbase,
                                         int m0, int n0, int k0, int tid) {
#pragma unroll
    for (int q = 0; q < 2; ++q) {
        int job = q * 256 + tid;
        int row = job >> 2, kg = job & 3;
        size_t src = (size_t)(m0 + row) * DD + k0 + kg * 8;
        uint32_t off = bufbase + (uint32_t)(row * ST_B + kg * 16);
        cp16(sb + SB_AHI + off, g_xhi + src);
        cp16(sb + SB_ALO + off, g_xlo + src);
    }
#pragma unroll
    for (int q = 0; q < 2; ++q) {
        int job = q * 256 + tid;
        int row = job >> 2, kg = job & 3;
        size_t src = (size_t)(n0 + row) * DD + k0 + kg * 8;
        uint32_t off = bufbase + (uint32_t)(row * ST_B + kg * 16);
        cp16(sb + SB_WHI + off, g_whi + src);
        cp16(sb + SB_WLO + off, g_wlo + src);
    }
}

__global__ __launch_bounds__(256) void xproj_mma_kernel(
    const float* __restrict__ bx,
    float* __restrict__ C)
{
    extern __shared__ char smem[];
    const uint32_t sb = smem_u32(smem);
    const int tid = threadIdx.x;
    const int wid = tid >> 5;
    const int l   = tid & 31;
    const int warp_m = wid & 3;
    const int warp_n = wid >> 2;
    const int m0 = blockIdx.x * 128;
    const int n0 = blockIdx.y * 128;

    float acc[2][8][4];
#pragma unroll
    for (int t = 0; t < 2; t++)
#pragma unroll
        for (int nb = 0; nb < 8; nb++)
#pragma unroll
            for (int i = 0; i < 4; i++) acc[t][nb][i] = 0.0f;

    const uint32_t aRowOff = (uint32_t)((warp_m * 32 + (l & 15)) * ST_B +
                                        (l >> 4) * 16);
    const uint32_t bRowOff = (uint32_t)((warp_n * 64 + ((l >> 4) << 3) + (l & 7)) * ST_B +
                                        ((l >> 3) & 1) * 16);

    stage_sc(sb, 0, m0, n0, 0, tid);
    CP_COMMIT();

#pragma unroll
    for (int sc = 0; sc < NSC; ++sc) {
        if (sc < NSC - 1) {
            stage_sc(sb, (uint32_t)(((sc + 1) & 1) * SB_BUF), m0, n0,
                     (sc + 1) * SC_K, tid);
            CP_COMMIT();
            cp_wait<1>();
        } else {
            cp_wait<0>();
        }
        __syncthreads();

        const uint32_t base = (uint32_t)((sc & 1) * SB_BUF);
#pragma unroll
        for (int ks = 0; ks < 2; ++ks) {
            const uint32_t kOff = (uint32_t)(ks * 32);
            uint32_t ahi[2][4], alo[2][4];
#pragma unroll
            for (int t = 0; t < 2; t++) {
                uint32_t abase = base + aRowOff + (uint32_t)(t * 16 * ST_B) + kOff;
                ldm_x4(ahi[t][0], ahi[t][1], ahi[t][2], ahi[t][3], sb + SB_AHI + abase);
                ldm_x4(alo[t][0], alo[t][1], alo[t][2], alo[t][3], sb + SB_ALO + abase);
            }
#pragma unroll
            for (int g = 0; g < 4; ++g) {
                uint32_t bbase = base + bRowOff + (uint32_t)(g * 16 * ST_B) + kOff;
                uint32_t h0, h1, h2, h3, q0, q1, q2, q3;
                ldm_x4(h0, h1, h2, h3, sb + SB_WHI + bbase);
                ldm_x4(q0, q1, q2, q3, sb + SB_WLO + bbase);
#pragma unroll
                for (int t = 0; t < 2; t++) {
                    mma16816(acc[t][2 * g],     ahi[t], h0, h1);
                    mma16816(acc[t][2 * g + 1], ahi[t], h2, h3);
                    mma16816(acc[t][2 * g],     alo[t], h0, h1);
                    mma16816(acc[t][2 * g + 1], alo[t], h2, h3);
                    mma16816(acc[t][2 * g],     ahi[t], q0, q1);
                    mma16816(acc[t][2 * g + 1], ahi[t], q2, q3);
                }
            }
        }
        __syncthreads();
    }

    const int mrow = m0 + warp_m * 32 + (l >> 2);
    const int ncol = n0 + warp_n * 64 + 2 * (l & 3);
#pragma unroll
    for (int t = 0; t < 2; t++) {
#pragma unroll
        for (int nb = 0; nb < 8; nb++) {
            int nn = ncol + nb * 8;
            float2 bv = *(const float2*)(bx + nn);
            int r0 = mrow + t * 16;
            float2 o0 = make_float2(acc[t][nb][0] + bv.x, acc[t][nb][1] + bv.y);
            float2 o1 = make_float2(acc[t][nb][2] + bv.x, acc[t][nb][3] + bv.y);
            *(float2*)(C + (size_t)r0 * HH + nn) = o0;
            *(float2*)(C + (size_t)(r0 + 8) * HH + nn) = o1;
        }
    }
}

// ====================================================================
// Kernel 2: scan — R16 structure (lane-paired halves, shuffle combine,
// 1 barrier/step, padded hbuf, tanhf, hoisted final store) with the
// register budget reshuffled: 100 weight floats in regs (25 f32x2 pairs),
// 28 in smem (7 float4/thread), 2 accumulators instead of 4.
// ====================================================================
#define HPAD 264   // 128 + 8 + 128 floats per h snapshot

__global__ __launch_bounds__(512, 1) void scan_kernel(
    const float* __restrict__ h0,
    const float* __restrict__ Wh,
    const float* __restrict__ bh,
    float* __restrict__ out,
    int hasFinal)
{
    extern __shared__ float smemf[];
    float4* Wsm  = (float4*)smemf;           // [7][512] float4 = 56 KB
    float*  hbuf = smemf + 7 * 512 * 4;      // 2 * HPAD floats (ping-pong)

    const int tid  = threadIdx.x;
    const int j    = tid >> 1;
    const int half = tid & 1;
    const int b    = blockIdx.x;
    const int kb   = half * 128;

    // register-resident weights: k in [kb, kb+100) as 25 packed f32x2 pairs
    ulonglong2 wu[25];
    const ulonglong2* wrow = (const ulonglong2*)(Wh + (size_t)j * HH + kb);
#pragma unroll
    for (int i = 0; i < 25; i++) wu[i] = wrow[i];

    // smem weights: k in [kb+100, kb+128), laid out [g][tid] (conflict-free)
    const float4* wrow4 = (const float4*)(Wh + (size_t)j * HH + kb);
#pragma unroll
    for (int g = 0; g < 7; ++g)
        Wsm[g * 512 + tid] = wrow4[25 + g];

    if (tid < 256) {
        int pos = tid + ((tid >> 7) << 3);   // +8 pad for upper half
        hbuf[pos] = h0[(size_t)b * HH + tid];
    }
    const float bh_r = bh[j];
    float* const outp = out + (size_t)b * HH + j;   // step stride SS

    float xp_next = outp[0];
    __syncthreads();

    const int hpos = j + ((j >> 7) << 3);
    int cur = 0;
    for (int t = 0; t < LL; ++t) {
        const float xp = xp_next;
        if (t + 1 < LL) xp_next = outp[(size_t)(t + 1) * SS];

        const ulonglong2* h2 = (const ulonglong2*)(hbuf + cur * HPAD + half * 136);
        unsigned long long p0 = 0ULL, p1 = 0ULL;
#pragma unroll
        for (int i = 0; i < 25; i++) {
            ulonglong2 hv = h2[i];
            p0 = ffma2(wu[i].x, hv.x, p0);
            p1 = ffma2(wu[i].y, hv.y, p1);
        }
        const ulonglong2* ws2 = (const ulonglong2*)Wsm;
#pragma unroll
        for (int g = 0; g < 7; g++) {
            ulonglong2 wv = ws2[(size_t)g * 512 + tid];
            ulonglong2 hv = h2[25 + g];
            p0 = ffma2(wv.x, hv.x, p0);
            p1 = ffma2(wv.y, hv.y, p1);
        }
        float acc = upk_sum(p0) + upk_sum(p1);
        float other = __shfl_xor_sync(0xFFFFFFFFu, acc, 1);
        float hn = tanhf(acc + other + xp + bh_r);

        if (!half) {
            hbuf[(cur ^ 1) * HPAD + hpos] = hn;
        } else {
            outp[(size_t)t * SS] = hn;
        }
        __syncthreads();
        cur ^= 1;
    }

    // final state h_L (hoisted out of the loop)
    if (hasFinal && half) {
        outp[(size_t)LL * SS] = outp[(size_t)(LL - 1) * SS];
    }
}

// ====================================================================
// launch
// ====================================================================
extern "C" void kernel_launch(void* const* d_in, const int* in_sizes, int n_in,
                              void* d_out, int out_size)
{
    const float* x   = (const float*)d_in[0];
    const float* h0  = (const float*)d_in[1];
    const float* Wxw = (const float*)d_in[2];
    const float* Wxb = (const float*)d_in[3];
    const float* Whw = (const float*)d_in[4];
    const float* Whb = (const float*)d_in[5];
    float* out = (float*)d_out;

    (void)in_sizes; (void)n_in;

    cudaFuncSetAttribute(xproj_mma_kernel, cudaFuncAttributeMaxDynamicSharedMemorySize, XP_SMEM);
    const int smemScan = (7 * 512 * 4 + 2 * HPAD) * (int)sizeof(float);   // 59456
    cudaFuncSetAttribute(scan_kernel, cudaFuncAttributeMaxDynamicSharedMemorySize, smemScan);

    convert_kernel<<<(CV_JOBS + 255) / 256, 256>>>(x, Wxw);

    dim3 g1(LL * BB / 128, HH / 128);   // (1024, 2) — R13 order, known good
    xproj_mma_kernel<<<g1, 256, XP_SMEM>>>(Wxb, out);

    const int hasFinal = (out_size >= LL * BB * HH + BB * HH) ? 1 : 0;
    scan_kernel<<<BB, 512, smemScan>>>(h0, Whw, Whb, out, hasFinal);
}